// round 16
// baseline (speedup 1.0000x reference)
#include <cuda_runtime.h>

#define T_  256
#define B_  1024
#define NX_ 256
#define NY_ 64
#define NU_ 64
#define ND_ 32
#define TB_ (T_*B_)

typedef unsigned long long ull;

// ---- device globals ----
__device__ float  g_WxT [NX_*NX_];   // [k][j]
__device__ float  g_WudT[96*NX_];    // [k][j]
__device__ float  g_WyT [NX_*NY_];   // [k][j]
__device__ double g_acc[6];          // 0:sxmin 1:sxmax 2:sumin 3:sumax 4:sdx 5:dxd

// ---- packed fp32x2 helpers ----
__device__ __forceinline__ ull pk2(float lo, float hi){
    ull r;
    asm("mov.b64 %0, {%1, %2};" : "=l"(r) : "f"(lo), "f"(hi));
    return r;
}
__device__ __forceinline__ void upk2(ull v, float& lo, float& hi){
    asm("mov.b64 {%0, %1}, %2;" : "=f"(lo), "=f"(hi) : "l"(v));
}
__device__ __forceinline__ ull fma2(ull a, ull b, ull c){
    ull d;
    asm("fma.rn.f32x2 %0, %1, %2, %3;" : "=l"(d) : "l"(a), "l"(b), "l"(c));
    return d;
}
__device__ __forceinline__ float warp_sum(float v){
    #pragma unroll
    for (int o = 16; o > 0; o >>= 1) v += __shfl_down_sync(0xffffffffu, v, o);
    return v;
}

// ============================================================================
// K0
// ============================================================================
__global__ void k0_prep(const float* __restrict__ Wx, const float* __restrict__ Wu,
                        const float* __restrict__ Wd, const float* __restrict__ Wy){
    int tid = blockIdx.x * blockDim.x + threadIdx.x;
    int nt  = gridDim.x * blockDim.x;
    if (blockIdx.x == 0 && threadIdx.x < 6) g_acc[threadIdx.x] = 0.0;
    for (int i = tid; i < NX_*NX_; i += nt){ int j = i / NX_, k = i % NX_; g_WxT[k*NX_ + j] = Wx[i]; }
    for (int i = tid; i < NX_*NU_; i += nt){ int j = i / NU_, k = i % NU_; g_WudT[k*NX_ + j] = Wu[i]; }
    for (int i = tid; i < NX_*ND_; i += nt){ int j = i / ND_, k = i % ND_; g_WudT[(64 + k)*NX_ + j] = Wd[i]; }
    for (int i = tid; i < NY_*NX_; i += nt){ int j = i / NX_, k = i % NX_; g_WyT[k*NY_ + j] = Wy[i]; }
}

// ============================================================================
// K1: S = fu + fd + bx. CTA = 128 rows x 64 cols, thread = 8r x 4c.
//     Weights staged in smem. [R9/R10 proven]
// ============================================================================
__global__ __launch_bounds__(256, 2) void k1_fud(const float* __restrict__ U,
                                                 const float* __restrict__ D,
                                                 const float* __restrict__ bx,
                                                 const float* __restrict__ bu,
                                                 const float* __restrict__ bd,
                                                 float* __restrict__ Xout){
    __shared__ __align__(16) float uds[96*132];
    __shared__ __align__(16) float ws[96*64];
    __shared__ float red[24];

    const int tid = threadIdx.x;
    const long g0 = (long)blockIdx.x * 128;
    const int cb  = blockIdx.y * 64;

    for (int idx = tid; idx < 96*64; idx += 256){
        int k = idx >> 6, c = idx & 63;
        ws[idx] = g_WudT[k*NX_ + cb + c];
    }
    for (int idx = tid; idx < 128*64; idx += 256){
        int r = idx >> 6, k = idx & 63;
        uds[k*132 + r] = U[(g0 + r)*NU_ + k];
    }
    for (int idx = tid; idx < 128*32; idx += 256){
        int r = idx >> 5, k = idx & 31;
        uds[(64 + k)*132 + r] = D[(g0 + r)*ND_ + k];
    }
    __syncthreads();

    const int r0 = (tid >> 4) * 8;
    const int cl = (tid & 15) * 4;
    const int c0 = cb + cl;

    ull accu[16], accd[16];
    #pragma unroll
    for (int i = 0; i < 16; i++){ accu[i] = 0ull; accd[i] = 0ull; }

    #pragma unroll 4
    for (int k = 0; k < 64; k++){
        float4 w = *(const float4*)&ws[k*64 + cl];
        ull w2[4] = { pk2(w.x, w.x), pk2(w.y, w.y), pk2(w.z, w.z), pk2(w.w, w.w) };
        ulonglong2 qa = *(const ulonglong2*)&uds[k*132 + r0];
        ulonglong2 qb = *(const ulonglong2*)&uds[k*132 + r0 + 4];
        #pragma unroll
        for (int c = 0; c < 4; c++){
            accu[c*4 + 0] = fma2(qa.x, w2[c], accu[c*4 + 0]);
            accu[c*4 + 1] = fma2(qa.y, w2[c], accu[c*4 + 1]);
            accu[c*4 + 2] = fma2(qb.x, w2[c], accu[c*4 + 2]);
            accu[c*4 + 3] = fma2(qb.y, w2[c], accu[c*4 + 3]);
        }
    }
    #pragma unroll 4
    for (int k = 64; k < 96; k++){
        float4 w = *(const float4*)&ws[k*64 + cl];
        ull w2[4] = { pk2(w.x, w.x), pk2(w.y, w.y), pk2(w.z, w.z), pk2(w.w, w.w) };
        ulonglong2 qa = *(const ulonglong2*)&uds[k*132 + r0];
        ulonglong2 qb = *(const ulonglong2*)&uds[k*132 + r0 + 4];
        #pragma unroll
        for (int c = 0; c < 4; c++){
            accd[c*4 + 0] = fma2(qa.x, w2[c], accd[c*4 + 0]);
            accd[c*4 + 1] = fma2(qa.y, w2[c], accd[c*4 + 1]);
            accd[c*4 + 2] = fma2(qb.x, w2[c], accd[c*4 + 2]);
            accd[c*4 + 3] = fma2(qb.y, w2[c], accd[c*4 + 3]);
        }
    }

    float s0 = 0.f, s1 = 0.f, s2 = 0.f;
    float vout[8][4];
    #pragma unroll
    for (int c = 0; c < 4; c++){
        float buc = bu[c0 + c], bdc = bd[c0 + c], bxc = bx[c0 + c];
        #pragma unroll
        for (int p = 0; p < 4; p++){
            float fu0, fu1, fd0, fd1;
            upk2(accu[c*4 + p], fu0, fu1);
            upk2(accd[c*4 + p], fd0, fd1);
            fu0 += buc; fu1 += buc; fd0 += bdc; fd1 += bdc;
            s0 += fmaxf(-fu0 - 1.f, 0.f) + fmaxf(-fu1 - 1.f, 0.f);
            s1 += fmaxf( fu0 - 1.f, 0.f) + fmaxf( fu1 - 1.f, 0.f);
            s2 += fmaxf(-fd0 - 1.f, 0.f) + fmaxf(fd0 - 1.f, 0.f)
                + fmaxf(-fd1 - 1.f, 0.f) + fmaxf(fd1 - 1.f, 0.f);
            vout[2*p    ][c] = fu0 + fd0 + bxc;
            vout[2*p + 1][c] = fu1 + fd1 + bxc;
        }
    }
    #pragma unroll
    for (int rr = 0; rr < 8; rr++){
        float4 o = make_float4(vout[rr][0], vout[rr][1], vout[rr][2], vout[rr][3]);
        *(float4*)&Xout[(g0 + r0 + rr)*NX_ + c0] = o;
    }

    s0 = warp_sum(s0); s1 = warp_sum(s1); s2 = warp_sum(s2);
    int lane = tid & 31, w = tid >> 5;
    if (lane == 0){ red[w] = s0; red[8 + w] = s1; red[16 + w] = s2; }
    __syncthreads();
    if (tid == 0){
        float a = 0, b = 0, c = 0;
        #pragma unroll
        for (int i = 0; i < 8; i++){ a += red[i]; b += red[8 + i]; c += red[16 + i]; }
        atomicAdd(&g_acc[2], (double)a);
        atomicAdd(&g_acc[3], (double)b);
        atomicAdd(&g_acc[5], (double)c);
    }
}

// ============================================================================
// K2: recurrence. 128 CTAs x 8 rows, 512 threads = 128 col-pairs x 4
//     k-quarters (4 warps/SMSP). Inner loop = R8's proven 8-chain fma2 /
//     float2-weight pattern. Quarter q: 44 cached k-rows (smem) + 20 streamed
//     (batch-20 prefetch covered by the 44 cached steps).
//     Epilogue: 2 threads/column, 4 rows each, summing 4 partial planes.
//     SMEM BUDGET (floats): wc 4*44*256=45056 | xcT 2048 | ps 4*8*256=8192
//     | red 48  -> 55344 floats = 221376 B (< 227KB cap).
// ============================================================================
#define K2_WC_FLOATS   (4*44*256)
#define K2_SMEM_FLOATS (K2_WC_FLOATS + 2048 + 8192 + 48)
#define K2_SMEM_BYTES  (K2_SMEM_FLOATS * 4)
static_assert(K2_SMEM_BYTES <= 227*1024, "k2 smem exceeds sm_103a cap");

__global__ __launch_bounds__(512, 1) void k2_rec(const float* __restrict__ x0,
                                                 float* __restrict__ Xout){
    extern __shared__ __align__(16) float sm[];
    float* wc  = sm;                              // [q][kl<44][j<256]
    float* xcT = sm + K2_WC_FLOATS;               // [k][m]
    float* ps  = sm + K2_WC_FLOATS + 2048;        // [q][m][j]
    float* red = sm + K2_WC_FLOATS + 2048 + 8192; // 48

    const int tid = threadIdx.x;
    const int kh  = tid >> 7;                // k-quarter 0..3
    const int c0  = (tid & 127) * 2;         // owned column pair (mainloop)
    const long rb = (long)blockIdx.x * 8;

    // cache: quarter q holds global k-rows q*64 + [0,44)  (44*256=11264 floats/q)
    for (int idx = tid; idx < K2_WC_FLOATS/4; idx += 512){
        int f   = idx * 4;
        int q   = f / 11264;
        int rem = f % 11264;
        int kl  = rem >> 8;
        int j   = rem & 255;
        *(float4*)&wc[f] = *(const float4*)&g_WxT[(q*64 + kl)*NX_ + j];
    }
    for (int idx = tid; idx < 8*NX_; idx += 512){
        int m = idx >> 8, k = idx & 255;
        xcT[k*8 + m] = x0[(rb + m)*NX_ + k];
    }
    __syncthreads();

    float sxmin = 0.f, sxmax = 0.f, sdx = 0.f;

    const float* wsbase = wc + (kh*44)*NX_ + c0;            // cached rows [0,44)
    const float* wgbase = g_WxT + (kh*64 + 44)*NX_ + c0;    // streamed rows [44,64)
    const float* xbase  = xcT + (kh*64)*8;
    float* psme = ps + kh*2048;

    // epilogue ownership: column je, rows m0..m0+3
    const int je = tid & 255;
    const int m0 = (tid >> 8) * 4;

    for (int t = 0; t < T_; t++){
        float* Srow = Xout + ((long)t*B_ + rb)*NX_;

        // epilogue S inputs, issued early
        float sv0 = Srow[(m0 + 0)*NX_ + je];
        float sv1 = Srow[(m0 + 1)*NX_ + je];
        float sv2 = Srow[(m0 + 2)*NX_ + je];
        float sv3 = Srow[(m0 + 3)*NX_ + je];

        ull a0[4] = {0,0,0,0}, a1[4] = {0,0,0,0};
        float2 wg[20];

        // P: prefetch streamed rows [44,64) of this quarter (MLP=20)
        #pragma unroll
        for (int i = 0; i < 20; i++) wg[i] = *(const float2*)(wgbase + i*NX_);

        // S: 44 cached k-steps
        #pragma unroll 4
        for (int k = 0; k < 44; k++){
            float2 w = *(const float2*)(wsbase + k*NX_);
            const ulonglong2* xr = (const ulonglong2*)(xbase + k*8);
            ulonglong2 q0 = xr[0], q1 = xr[1];
            ull w20 = pk2(w.x, w.x), w21 = pk2(w.y, w.y);
            a0[0] = fma2(q0.x, w20, a0[0]); a0[1] = fma2(q0.y, w20, a0[1]);
            a0[2] = fma2(q1.x, w20, a0[2]); a0[3] = fma2(q1.y, w20, a0[3]);
            a1[0] = fma2(q0.x, w21, a1[0]); a1[1] = fma2(q0.y, w21, a1[1]);
            a1[2] = fma2(q1.x, w21, a1[2]); a1[3] = fma2(q1.y, w21, a1[3]);
        }
        // C: 20 streamed k-steps
        #pragma unroll
        for (int i = 0; i < 20; i++){
            const ulonglong2* xr = (const ulonglong2*)(xbase + (44 + i)*8);
            ulonglong2 q0 = xr[0], q1 = xr[1];
            ull w20 = pk2(wg[i].x, wg[i].x), w21 = pk2(wg[i].y, wg[i].y);
            a0[0] = fma2(q0.x, w20, a0[0]); a0[1] = fma2(q0.y, w20, a0[1]);
            a0[2] = fma2(q1.x, w20, a0[2]); a0[3] = fma2(q1.y, w20, a0[3]);
            a1[0] = fma2(q0.x, w21, a1[0]); a1[1] = fma2(q0.y, w21, a1[1]);
            a1[2] = fma2(q1.x, w21, a1[2]); a1[3] = fma2(q1.y, w21, a1[3]);
        }

        // dump partials: ps[kh][m][c0..c0+1]
        {
            float f0[8], f1[8];
            #pragma unroll
            for (int p = 0; p < 4; p++){
                upk2(a0[p], f0[2*p], f0[2*p+1]);
                upk2(a1[p], f1[2*p], f1[2*p+1]);
            }
            #pragma unroll
            for (int m = 0; m < 8; m++)
                *(float2*)&psme[m*NX_ + c0] = make_float2(f0[m], f1[m]);
        }
        __syncthreads();

        // epilogue: thread owns col je, rows m0..m0+3
        {
            float4 xo = *(const float4*)&xcT[je*8 + m0];
            float v0 = sv0, v1 = sv1, v2 = sv2, v3 = sv3;
            #pragma unroll
            for (int q = 0; q < 4; q++){
                const float* pq = ps + q*2048 + je;
                v0 += pq[(m0 + 0)*NX_];
                v1 += pq[(m0 + 1)*NX_];
                v2 += pq[(m0 + 2)*NX_];
                v3 += pq[(m0 + 3)*NX_];
            }
            sxmin += fmaxf(-v0-1.f,0.f) + fmaxf(-v1-1.f,0.f) + fmaxf(-v2-1.f,0.f) + fmaxf(-v3-1.f,0.f);
            sxmax += fmaxf( v0-1.f,0.f) + fmaxf( v1-1.f,0.f) + fmaxf( v2-1.f,0.f) + fmaxf( v3-1.f,0.f);
            float d0 = v0-xo.x, d1 = v1-xo.y, d2 = v2-xo.z, d3 = v3-xo.w;
            sdx += d0*d0 + d1*d1 + d2*d2 + d3*d3;
            Srow[(m0+0)*NX_ + je] = v0;
            Srow[(m0+1)*NX_ + je] = v1;
            Srow[(m0+2)*NX_ + je] = v2;
            Srow[(m0+3)*NX_ + je] = v3;
            *(float4*)&xcT[je*8 + m0] = make_float4(v0, v1, v2, v3);
        }
        __syncthreads();
    }

    sxmin = warp_sum(sxmin); sxmax = warp_sum(sxmax); sdx = warp_sum(sdx);
    int lane = tid & 31, w = tid >> 5;
    if (lane == 0){ red[w] = sxmin; red[16 + w] = sxmax; red[32 + w] = sdx; }
    __syncthreads();
    if (tid == 0){
        float a = 0, b = 0, c = 0;
        #pragma unroll
        for (int i = 0; i < 16; i++){ a += red[i]; b += red[16 + i]; c += red[32 + i]; }
        atomicAdd(&g_acc[0], (double)a);
        atomicAdd(&g_acc[1], (double)b);
        atomicAdd(&g_acc[4], (double)c);
    }
}

// ============================================================================
// K3: Y = X @ Wy^T + by. CTA = 128 rows x 64 cols, thread = 8r x 4c,
//     K staged in 4 chunks of 64; weights staged in smem. [R9/R10 proven]
// ============================================================================
__global__ __launch_bounds__(256, 4) void k3_y(const float* __restrict__ Xout,
                                               const float* __restrict__ by,
                                               float* __restrict__ Yout){
    __shared__ __align__(16) float xs[64*132];
    __shared__ __align__(16) float ws[64*64];
    const int tid = threadIdx.x;
    const long g0 = (long)blockIdx.x * 128;
    const int r0 = (tid >> 4) * 8;
    const int c0 = (tid & 15) * 4;

    ull acc[16];
    #pragma unroll
    for (int i = 0; i < 16; i++) acc[i] = 0ull;

    for (int ch = 0; ch < 4; ch++){
        if (ch) __syncthreads();
        for (int idx = tid; idx < 128*64; idx += 256){
            int r = idx >> 6, k = idx & 63;
            xs[k*132 + r] = Xout[(g0 + r)*NX_ + ch*64 + k];
        }
        for (int idx = tid; idx < 64*64; idx += 256){
            int k = idx >> 6, c = idx & 63;
            ws[idx] = g_WyT[(ch*64 + k)*NY_ + c];
        }
        __syncthreads();

        #pragma unroll 4
        for (int k = 0; k < 64; k++){
            float4 w = *(const float4*)&ws[k*64 + c0];
            ull w2[4] = { pk2(w.x, w.x), pk2(w.y, w.y), pk2(w.z, w.z), pk2(w.w, w.w) };
            ulonglong2 qa = *(const ulonglong2*)&xs[k*132 + r0];
            ulonglong2 qb = *(const ulonglong2*)&xs[k*132 + r0 + 4];
            #pragma unroll
            for (int c = 0; c < 4; c++){
                acc[c*4 + 0] = fma2(qa.x, w2[c], acc[c*4 + 0]);
                acc[c*4 + 1] = fma2(qa.y, w2[c], acc[c*4 + 1]);
                acc[c*4 + 2] = fma2(qb.x, w2[c], acc[c*4 + 2]);
                acc[c*4 + 3] = fma2(qb.y, w2[c], acc[c*4 + 3]);
            }
        }
    }

    float byv[4] = { by[c0], by[c0+1], by[c0+2], by[c0+3] };
    float vout[8][4];
    #pragma unroll
    for (int c = 0; c < 4; c++){
        #pragma unroll
        for (int p = 0; p < 4; p++){
            float lo, hi;
            upk2(acc[c*4 + p], lo, hi);
            vout[2*p    ][c] = lo + byv[c];
            vout[2*p + 1][c] = hi + byv[c];
        }
    }
    #pragma unroll
    for (int rr = 0; rr < 8; rr++){
        float4 o = make_float4(vout[rr][0], vout[rr][1], vout[rr][2], vout[rr][3]);
        *(float4*)&Yout[(g0 + r0 + rr)*NY_ + c0] = o;
    }
}

// ============================================================================
// K4
// ============================================================================
__global__ void k4_fin(float* __restrict__ out_reg){
    double inv = 1.0 / ((double)T_ * (double)B_ * (double)NX_);
    double s = g_acc[0] + g_acc[1] + 2.0*(g_acc[2] + g_acc[3]) + g_acc[4] + g_acc[5];
    *out_reg = (float)(0.2 * s * inv);
}

extern "C" void kernel_launch(void* const* d_in, const int* in_sizes, int n_in,
                              void* d_out, int out_size){
    const float* x  = (const float*)d_in[0];
    const float* U  = (const float*)d_in[1];
    const float* D  = (const float*)d_in[2];
    const float* Wx = (const float*)d_in[3];
    const float* bx = (const float*)d_in[4];
    const float* Wu = (const float*)d_in[5];
    const float* bu = (const float*)d_in[6];
    const float* Wd = (const float*)d_in[7];
    const float* bd = (const float*)d_in[8];
    const float* Wy = (const float*)d_in[9];
    const float* by = (const float*)d_in[10];

    float* out  = (float*)d_out;
    float* Xout = out;
    float* Yout = out + (size_t)TB_ * NX_;
    float* Rout = out + (size_t)TB_ * NX_ + (size_t)TB_ * NY_;

    cudaFuncSetAttribute(k2_rec, cudaFuncAttributeMaxDynamicSharedMemorySize,
                         K2_SMEM_BYTES);

    k0_prep<<<256, 256>>>(Wx, Wu, Wd, Wy);
    k1_fud<<<dim3(TB_/128, 4), 256>>>(U, D, bx, bu, bd, Xout);
    k2_rec<<<B_/8, 512, K2_SMEM_BYTES>>>(x, Xout);
    k3_y<<<TB_/128, 256>>>(Xout, by, Yout);
    k4_fin<<<1, 1>>>(Rout);
}

// round 17
// speedup vs baseline: 1.1177x; 1.1177x over previous
#include <cuda_runtime.h>

#define T_  256
#define B_  1024
#define NX_ 256
#define NY_ 64
#define NU_ 64
#define ND_ 32
#define TB_ (T_*B_)

typedef unsigned long long ull;

// ---- device globals ----
__device__ float  g_WxT [NX_*NX_];   // [k][j]
__device__ float  g_WudT[96*NX_];    // [k][j]
__device__ float  g_WyT [NX_*NY_];   // [k][j]
__device__ double g_acc[6];          // 0:sxmin 1:sxmax 2:sumin 3:sumax 4:sdx 5:dxd

// ---- packed fp32x2 helpers ----
__device__ __forceinline__ ull pk2(float lo, float hi){
    ull r;
    asm("mov.b64 %0, {%1, %2};" : "=l"(r) : "f"(lo), "f"(hi));
    return r;
}
__device__ __forceinline__ void upk2(ull v, float& lo, float& hi){
    asm("mov.b64 {%0, %1}, %2;" : "=f"(lo), "=f"(hi) : "l"(v));
}
__device__ __forceinline__ ull fma2(ull a, ull b, ull c){
    ull d;
    asm("fma.rn.f32x2 %0, %1, %2, %3;" : "=l"(d) : "l"(a), "l"(b), "l"(c));
    return d;
}
__device__ __forceinline__ float warp_sum(float v){
    #pragma unroll
    for (int o = 16; o > 0; o >>= 1) v += __shfl_down_sync(0xffffffffu, v, o);
    return v;
}

// ============================================================================
// K0
// ============================================================================
__global__ void k0_prep(const float* __restrict__ Wx, const float* __restrict__ Wu,
                        const float* __restrict__ Wd, const float* __restrict__ Wy){
    int tid = blockIdx.x * blockDim.x + threadIdx.x;
    int nt  = gridDim.x * blockDim.x;
    if (blockIdx.x == 0 && threadIdx.x < 6) g_acc[threadIdx.x] = 0.0;
    for (int i = tid; i < NX_*NX_; i += nt){ int j = i / NX_, k = i % NX_; g_WxT[k*NX_ + j] = Wx[i]; }
    for (int i = tid; i < NX_*NU_; i += nt){ int j = i / NU_, k = i % NU_; g_WudT[k*NX_ + j] = Wu[i]; }
    for (int i = tid; i < NX_*ND_; i += nt){ int j = i / ND_, k = i % ND_; g_WudT[(64 + k)*NX_ + j] = Wd[i]; }
    for (int i = tid; i < NY_*NX_; i += nt){ int j = i / NX_, k = i % NX_; g_WyT[k*NY_ + j] = Wy[i]; }
}

// ============================================================================
// K1: S = fu + fd + bx. CTA = 128 rows x 64 cols, thread = 8r x 4c.
//     Weights staged in smem. [R9/R10 proven]
// ============================================================================
__global__ __launch_bounds__(256, 2) void k1_fud(const float* __restrict__ U,
                                                 const float* __restrict__ D,
                                                 const float* __restrict__ bx,
                                                 const float* __restrict__ bu,
                                                 const float* __restrict__ bd,
                                                 float* __restrict__ Xout){
    __shared__ __align__(16) float uds[96*132];
    __shared__ __align__(16) float ws[96*64];
    __shared__ float red[24];

    const int tid = threadIdx.x;
    const long g0 = (long)blockIdx.x * 128;
    const int cb  = blockIdx.y * 64;

    for (int idx = tid; idx < 96*64; idx += 256){
        int k = idx >> 6, c = idx & 63;
        ws[idx] = g_WudT[k*NX_ + cb + c];
    }
    for (int idx = tid; idx < 128*64; idx += 256){
        int r = idx >> 6, k = idx & 63;
        uds[k*132 + r] = U[(g0 + r)*NU_ + k];
    }
    for (int idx = tid; idx < 128*32; idx += 256){
        int r = idx >> 5, k = idx & 31;
        uds[(64 + k)*132 + r] = D[(g0 + r)*ND_ + k];
    }
    __syncthreads();

    const int r0 = (tid >> 4) * 8;
    const int cl = (tid & 15) * 4;
    const int c0 = cb + cl;

    ull accu[16], accd[16];
    #pragma unroll
    for (int i = 0; i < 16; i++){ accu[i] = 0ull; accd[i] = 0ull; }

    #pragma unroll 4
    for (int k = 0; k < 64; k++){
        float4 w = *(const float4*)&ws[k*64 + cl];
        ull w2[4] = { pk2(w.x, w.x), pk2(w.y, w.y), pk2(w.z, w.z), pk2(w.w, w.w) };
        ulonglong2 qa = *(const ulonglong2*)&uds[k*132 + r0];
        ulonglong2 qb = *(const ulonglong2*)&uds[k*132 + r0 + 4];
        #pragma unroll
        for (int c = 0; c < 4; c++){
            accu[c*4 + 0] = fma2(qa.x, w2[c], accu[c*4 + 0]);
            accu[c*4 + 1] = fma2(qa.y, w2[c], accu[c*4 + 1]);
            accu[c*4 + 2] = fma2(qb.x, w2[c], accu[c*4 + 2]);
            accu[c*4 + 3] = fma2(qb.y, w2[c], accu[c*4 + 3]);
        }
    }
    #pragma unroll 4
    for (int k = 64; k < 96; k++){
        float4 w = *(const float4*)&ws[k*64 + cl];
        ull w2[4] = { pk2(w.x, w.x), pk2(w.y, w.y), pk2(w.z, w.z), pk2(w.w, w.w) };
        ulonglong2 qa = *(const ulonglong2*)&uds[k*132 + r0];
        ulonglong2 qb = *(const ulonglong2*)&uds[k*132 + r0 + 4];
        #pragma unroll
        for (int c = 0; c < 4; c++){
            accd[c*4 + 0] = fma2(qa.x, w2[c], accd[c*4 + 0]);
            accd[c*4 + 1] = fma2(qa.y, w2[c], accd[c*4 + 1]);
            accd[c*4 + 2] = fma2(qb.x, w2[c], accd[c*4 + 2]);
            accd[c*4 + 3] = fma2(qb.y, w2[c], accd[c*4 + 3]);
        }
    }

    float s0 = 0.f, s1 = 0.f, s2 = 0.f;
    float vout[8][4];
    #pragma unroll
    for (int c = 0; c < 4; c++){
        float buc = bu[c0 + c], bdc = bd[c0 + c], bxc = bx[c0 + c];
        #pragma unroll
        for (int p = 0; p < 4; p++){
            float fu0, fu1, fd0, fd1;
            upk2(accu[c*4 + p], fu0, fu1);
            upk2(accd[c*4 + p], fd0, fd1);
            fu0 += buc; fu1 += buc; fd0 += bdc; fd1 += bdc;
            s0 += fmaxf(-fu0 - 1.f, 0.f) + fmaxf(-fu1 - 1.f, 0.f);
            s1 += fmaxf( fu0 - 1.f, 0.f) + fmaxf( fu1 - 1.f, 0.f);
            s2 += fmaxf(-fd0 - 1.f, 0.f) + fmaxf(fd0 - 1.f, 0.f)
                + fmaxf(-fd1 - 1.f, 0.f) + fmaxf(fd1 - 1.f, 0.f);
            vout[2*p    ][c] = fu0 + fd0 + bxc;
            vout[2*p + 1][c] = fu1 + fd1 + bxc;
        }
    }
    #pragma unroll
    for (int rr = 0; rr < 8; rr++){
        float4 o = make_float4(vout[rr][0], vout[rr][1], vout[rr][2], vout[rr][3]);
        *(float4*)&Xout[(g0 + r0 + rr)*NX_ + c0] = o;
    }

    s0 = warp_sum(s0); s1 = warp_sum(s1); s2 = warp_sum(s2);
    int lane = tid & 31, w = tid >> 5;
    if (lane == 0){ red[w] = s0; red[8 + w] = s1; red[16 + w] = s2; }
    __syncthreads();
    if (tid == 0){
        float a = 0, b = 0, c = 0;
        #pragma unroll
        for (int i = 0; i < 8; i++){ a += red[i]; b += red[8 + i]; c += red[16 + i]; }
        atomicAdd(&g_acc[2], (double)a);
        atomicAdd(&g_acc[3], (double)b);
        atomicAdd(&g_acc[5], (double)c);
    }
}

// ============================================================================
// K2: recurrence. 128 CTAs x 8 rows, 256 threads = 4 k-quarters x 64 threads,
//     thread = 8 rows x 4 cols (k1's proven shape: float4 weight LDS.128 +
//     2 broadcast x LDS.128 per 16 fma2 -> crossbar/FMA ratio 0.1875 vs 0.25).
//     Quarter q: 44 cached k-rows (smem) + 20 streamed (2x batch-10 float4
//     prefetch). Epilogue: thread owns one column, 8 rows, sums 4 planes.
//     SMEM (floats): wc 4*44*256=45056 | xcT 2048 | ps 4*8*256=8192 | red 48
// ============================================================================
#define K2_WC_FLOATS   (4*44*256)
#define K2_SMEM_FLOATS (K2_WC_FLOATS + 2048 + 8192 + 48)
#define K2_SMEM_BYTES  (K2_SMEM_FLOATS * 4)
static_assert(K2_SMEM_BYTES <= 227*1024, "k2 smem exceeds sm_103a cap");

__global__ __launch_bounds__(256, 1) void k2_rec(const float* __restrict__ x0,
                                                 float* __restrict__ Xout){
    extern __shared__ __align__(16) float sm[];
    float* wc  = sm;                              // [q][kl<44][j<256]
    float* xcT = sm + K2_WC_FLOATS;               // [k][m] 256*8
    float* ps  = sm + K2_WC_FLOATS + 2048;        // [q][m][j] 4*8*256
    float* red = sm + K2_WC_FLOATS + 2048 + 8192; // 48

    const int tid = threadIdx.x;
    const int q   = tid >> 6;                // k-quarter 0..3
    const int c0  = (tid & 63) * 4;          // owned 4-column group (mainloop)
    const long rb = (long)blockIdx.x * 8;

    // cache: quarter qq holds global k-rows qq*64 + [0,44)
    for (int idx = tid; idx < K2_WC_FLOATS/4; idx += 256){
        int f   = idx * 4;
        int qq  = f / 11264;
        int rem = f % 11264;
        int kl  = rem >> 8;
        int j   = rem & 255;
        *(float4*)&wc[f] = *(const float4*)&g_WxT[(qq*64 + kl)*NX_ + j];
    }
    for (int idx = tid; idx < 8*NX_; idx += 256){
        int m = idx >> 8, k = idx & 255;
        xcT[k*8 + m] = x0[(rb + m)*NX_ + k];
    }
    __syncthreads();

    float sxmin = 0.f, sxmax = 0.f, sdx = 0.f;

    const float* wsbase = wc + (q*44)*NX_ + c0;           // cached rows [0,44)
    const float* wgbase = g_WxT + (q*64 + 44)*NX_ + c0;   // streamed rows [44,64)
    const float* xbase  = xcT + (q*64)*8;
    float* psme = ps + q*2048;

    for (int t = 0; t < T_; t++){
        float* Srow = Xout + ((long)t*B_ + rb)*NX_;

        // epilogue S inputs (own column = tid), issued early
        float sv[8];
        #pragma unroll
        for (int m = 0; m < 8; m++) sv[m] = Srow[m*NX_ + tid];

        ull acc[16];
        #pragma unroll
        for (int i = 0; i < 16; i++) acc[i] = 0ull;

        float4 wg[10];

        // P A: prefetch streamed rows [44,54) (MLP=10)
        #pragma unroll
        for (int i = 0; i < 10; i++) wg[i] = *(const float4*)(wgbase + i*NX_);

        // S A: cached k [0,22)
        #pragma unroll 2
        for (int k = 0; k < 22; k++){
            float4 w = *(const float4*)(wsbase + k*NX_);
            ull w2[4] = { pk2(w.x, w.x), pk2(w.y, w.y), pk2(w.z, w.z), pk2(w.w, w.w) };
            ulonglong2 qa = *(const ulonglong2*)(xbase + k*8);
            ulonglong2 qb = *(const ulonglong2*)(xbase + k*8 + 4);
            #pragma unroll
            for (int c = 0; c < 4; c++){
                acc[c*4 + 0] = fma2(qa.x, w2[c], acc[c*4 + 0]);
                acc[c*4 + 1] = fma2(qa.y, w2[c], acc[c*4 + 1]);
                acc[c*4 + 2] = fma2(qb.x, w2[c], acc[c*4 + 2]);
                acc[c*4 + 3] = fma2(qb.y, w2[c], acc[c*4 + 3]);
            }
        }
        // C A: streamed k [44,54)
        #pragma unroll
        for (int i = 0; i < 10; i++){
            ull w2[4] = { pk2(wg[i].x, wg[i].x), pk2(wg[i].y, wg[i].y),
                          pk2(wg[i].z, wg[i].z), pk2(wg[i].w, wg[i].w) };
            ulonglong2 qa = *(const ulonglong2*)(xbase + (44 + i)*8);
            ulonglong2 qb = *(const ulonglong2*)(xbase + (44 + i)*8 + 4);
            #pragma unroll
            for (int c = 0; c < 4; c++){
                acc[c*4 + 0] = fma2(qa.x, w2[c], acc[c*4 + 0]);
                acc[c*4 + 1] = fma2(qa.y, w2[c], acc[c*4 + 1]);
                acc[c*4 + 2] = fma2(qb.x, w2[c], acc[c*4 + 2]);
                acc[c*4 + 3] = fma2(qb.y, w2[c], acc[c*4 + 3]);
            }
        }
        // P B: prefetch streamed rows [54,64)
        #pragma unroll
        for (int i = 0; i < 10; i++) wg[i] = *(const float4*)(wgbase + (10 + i)*NX_);

        // S B: cached k [22,44)
        #pragma unroll 2
        for (int k = 22; k < 44; k++){
            float4 w = *(const float4*)(wsbase + k*NX_);
            ull w2[4] = { pk2(w.x, w.x), pk2(w.y, w.y), pk2(w.z, w.z), pk2(w.w, w.w) };
            ulonglong2 qa = *(const ulonglong2*)(xbase + k*8);
            ulonglong2 qb = *(const ulonglong2*)(xbase + k*8 + 4);
            #pragma unroll
            for (int c = 0; c < 4; c++){
                acc[c*4 + 0] = fma2(qa.x, w2[c], acc[c*4 + 0]);
                acc[c*4 + 1] = fma2(qa.y, w2[c], acc[c*4 + 1]);
                acc[c*4 + 2] = fma2(qb.x, w2[c], acc[c*4 + 2]);
                acc[c*4 + 3] = fma2(qb.y, w2[c], acc[c*4 + 3]);
            }
        }
        // C B: streamed k [54,64)
        #pragma unroll
        for (int i = 0; i < 10; i++){
            ull w2[4] = { pk2(wg[i].x, wg[i].x), pk2(wg[i].y, wg[i].y),
                          pk2(wg[i].z, wg[i].z), pk2(wg[i].w, wg[i].w) };
            ulonglong2 qa = *(const ulonglong2*)(xbase + (54 + i)*8);
            ulonglong2 qb = *(const ulonglong2*)(xbase + (54 + i)*8 + 4);
            #pragma unroll
            for (int c = 0; c < 4; c++){
                acc[c*4 + 0] = fma2(qa.x, w2[c], acc[c*4 + 0]);
                acc[c*4 + 1] = fma2(qa.y, w2[c], acc[c*4 + 1]);
                acc[c*4 + 2] = fma2(qb.x, w2[c], acc[c*4 + 2]);
                acc[c*4 + 3] = fma2(qb.y, w2[c], acc[c*4 + 3]);
            }
        }

        // dump partials: ps[q][m][c0..c0+3] via float4 rows
        {
            float v[4][8];   // [c][m]
            #pragma unroll
            for (int c = 0; c < 4; c++)
                #pragma unroll
                for (int p = 0; p < 4; p++)
                    upk2(acc[c*4 + p], v[c][2*p], v[c][2*p + 1]);
            #pragma unroll
            for (int m = 0; m < 8; m++)
                *(float4*)&psme[m*NX_ + c0] = make_float4(v[0][m], v[1][m], v[2][m], v[3][m]);
        }
        __syncthreads();

        // epilogue: thread owns column tid, rows 0..7; sum 4 planes
        {
            float4 xo0 = *(const float4*)&xcT[tid*8];
            float4 xo1 = *(const float4*)&xcT[tid*8 + 4];
            float xold[8] = {xo0.x, xo0.y, xo0.z, xo0.w, xo1.x, xo1.y, xo1.z, xo1.w};
            float xn[8];
            #pragma unroll
            for (int m = 0; m < 8; m++){
                float v = sv[m]
                        + ps[0*2048 + m*NX_ + tid] + ps[1*2048 + m*NX_ + tid]
                        + ps[2*2048 + m*NX_ + tid] + ps[3*2048 + m*NX_ + tid];
                sxmin += fmaxf(-v - 1.f, 0.f);
                sxmax += fmaxf( v - 1.f, 0.f);
                float d = v - xold[m];
                sdx += d*d;
                Srow[m*NX_ + tid] = v;
                xn[m] = v;
            }
            *(float4*)&xcT[tid*8]     = make_float4(xn[0], xn[1], xn[2], xn[3]);
            *(float4*)&xcT[tid*8 + 4] = make_float4(xn[4], xn[5], xn[6], xn[7]);
        }
        __syncthreads();
    }

    sxmin = warp_sum(sxmin); sxmax = warp_sum(sxmax); sdx = warp_sum(sdx);
    int lane = tid & 31, w = tid >> 5;
    if (lane == 0){ red[w] = sxmin; red[8 + w] = sxmax; red[16 + w] = sdx; }
    __syncthreads();
    if (tid == 0){
        float a = 0, b = 0, c = 0;
        #pragma unroll
        for (int i = 0; i < 8; i++){ a += red[i]; b += red[8 + i]; c += red[16 + i]; }
        atomicAdd(&g_acc[0], (double)a);
        atomicAdd(&g_acc[1], (double)b);
        atomicAdd(&g_acc[4], (double)c);
    }
}

// ============================================================================
// K3: Y = X @ Wy^T + by. CTA = 128 rows x 64 cols, thread = 8r x 4c,
//     K staged in 4 chunks of 64; weights staged in smem. [R9/R10 proven]
// ============================================================================
__global__ __launch_bounds__(256, 4) void k3_y(const float* __restrict__ Xout,
                                               const float* __restrict__ by,
                                               float* __restrict__ Yout){
    __shared__ __align__(16) float xs[64*132];
    __shared__ __align__(16) float ws[64*64];
    const int tid = threadIdx.x;
    const long g0 = (long)blockIdx.x * 128;
    const int r0 = (tid >> 4) * 8;
    const int c0 = (tid & 15) * 4;

    ull acc[16];
    #pragma unroll
    for (int i = 0; i < 16; i++) acc[i] = 0ull;

    for (int ch = 0; ch < 4; ch++){
        if (ch) __syncthreads();
        for (int idx = tid; idx < 128*64; idx += 256){
            int r = idx >> 6, k = idx & 63;
            xs[k*132 + r] = Xout[(g0 + r)*NX_ + ch*64 + k];
        }
        for (int idx = tid; idx < 64*64; idx += 256){
            int k = idx >> 6, c = idx & 63;
            ws[idx] = g_WyT[(ch*64 + k)*NY_ + c];
        }
        __syncthreads();

        #pragma unroll 4
        for (int k = 0; k < 64; k++){
            float4 w = *(const float4*)&ws[k*64 + c0];
            ull w2[4] = { pk2(w.x, w.x), pk2(w.y, w.y), pk2(w.z, w.z), pk2(w.w, w.w) };
            ulonglong2 qa = *(const ulonglong2*)&xs[k*132 + r0];
            ulonglong2 qb = *(const ulonglong2*)&xs[k*132 + r0 + 4];
            #pragma unroll
            for (int c = 0; c < 4; c++){
                acc[c*4 + 0] = fma2(qa.x, w2[c], acc[c*4 + 0]);
                acc[c*4 + 1] = fma2(qa.y, w2[c], acc[c*4 + 1]);
                acc[c*4 + 2] = fma2(qb.x, w2[c], acc[c*4 + 2]);
                acc[c*4 + 3] = fma2(qb.y, w2[c], acc[c*4 + 3]);
            }
        }
    }

    float byv[4] = { by[c0], by[c0+1], by[c0+2], by[c0+3] };
    float vout[8][4];
    #pragma unroll
    for (int c = 0; c < 4; c++){
        #pragma unroll
        for (int p = 0; p < 4; p++){
            float lo, hi;
            upk2(acc[c*4 + p], lo, hi);
            vout[2*p    ][c] = lo + byv[c];
            vout[2*p + 1][c] = hi + byv[c];
        }
    }
    #pragma unroll
    for (int rr = 0; rr < 8; rr++){
        float4 o = make_float4(vout[rr][0], vout[rr][1], vout[rr][2], vout[rr][3]);
        *(float4*)&Yout[(g0 + r0 + rr)*NY_ + c0] = o;
    }
}

// ============================================================================
// K4
// ============================================================================
__global__ void k4_fin(float* __restrict__ out_reg){
    double inv = 1.0 / ((double)T_ * (double)B_ * (double)NX_);
    double s = g_acc[0] + g_acc[1] + 2.0*(g_acc[2] + g_acc[3]) + g_acc[4] + g_acc[5];
    *out_reg = (float)(0.2 * s * inv);
}

extern "C" void kernel_launch(void* const* d_in, const int* in_sizes, int n_in,
                              void* d_out, int out_size){
    const float* x  = (const float*)d_in[0];
    const float* U  = (const float*)d_in[1];
    const float* D  = (const float*)d_in[2];
    const float* Wx = (const float*)d_in[3];
    const float* bx = (const float*)d_in[4];
    const float* Wu = (const float*)d_in[5];
    const float* bu = (const float*)d_in[6];
    const float* Wd = (const float*)d_in[7];
    const float* bd = (const float*)d_in[8];
    const float* Wy = (const float*)d_in[9];
    const float* by = (const float*)d_in[10];

    float* out  = (float*)d_out;
    float* Xout = out;
    float* Yout = out + (size_t)TB_ * NX_;
    float* Rout = out + (size_t)TB_ * NX_ + (size_t)TB_ * NY_;

    cudaFuncSetAttribute(k2_rec, cudaFuncAttributeMaxDynamicSharedMemorySize,
                         K2_SMEM_BYTES);

    k0_prep<<<256, 256>>>(Wx, Wu, Wd, Wy);
    k1_fud<<<dim3(TB_/128, 4), 256>>>(U, D, bx, bu, bd, Xout);
    k2_rec<<<B_/8, 256, K2_SMEM_BYTES>>>(x, Xout);
    k3_y<<<TB_/128, 256>>>(Xout, by, Yout);
    k4_fin<<<1, 1>>>(Rout);
}